// round 16
// baseline (speedup 1.0000x reference)
#include <cuda_runtime.h>
#include <cstdint>

// ISTFT via half-size complex IFFT (radix-4 Stockham on 1024 pts).
// Stage 0 fused into pack (registers, contiguous float4 stores), stage 4
// fused into output (identity twiddles). Middle 3 stages in PLAIN smem
// (identical pattern to the proven R13 kernel). Then COLA overlap-add.
// Shapes: B=8, T=1000, F=1025, NFFT=2048, HOP=512.

#define NFFT   2048
#define FREQ   1025
#define HOPLEN 512
#define BATCH  8
#define N2     1024

__device__ __align__(256) float g_s[(size_t)BATCH * 1000 * NFFT];

__device__ __forceinline__ float2 cmul(float2 a, float2 b) {
    return make_float2(a.x * b.x - a.y * b.y, a.x * b.y + a.y * b.x);
}

// ---------------- kernel 1: per-frame windowed real IFFT --------------------
__global__ void __launch_bounds__(256)
ifft_kernel(const float* __restrict__ re, const float* __restrict__ im,
            const float* __restrict__ win, int T, int nf) {
    __shared__ float2 bufA[N2];
    __shared__ float2 bufB[N2];
    __shared__ float2 tw[256];        // e^{+2pi i j / 1024}

    const int frame = blockIdx.x;
    const int b = frame / nf;
    const int t = frame - b * nf;
    const size_t base = (size_t)(b * T + t) * FREQ;
    const int tid = threadIdx.x;

    // twiddles: tw1r (stage-0, register) and tw2 (pack) via 2 sincospif
    float2 tw1r, tw2;
    {
        float s, c;
        sincospif((float)tid / 512.0f, &s, &c);   // 2*pi*tid/1024
        tw1r = make_float2(c, s);
        tw[tid] = tw1r;
        sincospif((float)tid / 1024.0f, &s, &c);  // 2*pi*tid/2048
        tw2 = make_float2(c, s);
    }

    const float R = 0.70710678118654752f;
    const float2 rot[4] = { make_float2(1.f, 0.f), make_float2(R, R),
                            make_float2(0.f, 1.f), make_float2(-R, R) };

    // ---- pack Z[k] in registers (k = tid + 256u) + fused stage 0 (s=1) ----
    float2 z[4];
#pragma unroll
    for (int u = 0; u < 4; u++) {
        const int k = tid + u * 256;
        float2 Fk, F2;
        if (k == 0) {
            Fk = make_float2(__ldg(re + base), 0.f);
            F2 = make_float2(__ldg(re + base + N2), 0.f);
        } else {
            Fk = make_float2(__ldg(re + base + k), __ldg(im + base + k));
            F2 = make_float2(__ldg(re + base + (N2 - k)),
                             -__ldg(im + base + (N2 - k)));
        }
        const float2 A  = make_float2(Fk.x + F2.x, Fk.y + F2.y);
        const float2 Bc = make_float2(Fk.x - F2.x, Fk.y - F2.y);
        const float2 w  = cmul(tw2, rot[u]);
        const float2 Bt = cmul(Bc, w);
        z[u] = make_float2(A.x - Bt.y, A.y + Bt.x);
    }
    {   // stage 0: inputs z[u] = Z[tid + 256u]; outputs 4*tid .. 4*tid+3
        const float2 w1 = tw1r;
        const float2 w2 = cmul(w1, w1);
        const float2 w3 = cmul(w2, w1);
        const float2 s02 = make_float2(z[0].x + z[2].x, z[0].y + z[2].y);
        const float2 d02 = make_float2(z[0].x - z[2].x, z[0].y - z[2].y);
        const float2 s13 = make_float2(z[1].x + z[3].x, z[1].y + z[3].y);
        const float2 d13 = make_float2(z[1].x - z[3].x, z[1].y - z[3].y);
        const float2 o0 = make_float2(s02.x + s13.x, s02.y + s13.y);
        const float2 o1 = cmul(w1, make_float2(d02.x - d13.y, d02.y + d13.x));
        const float2 o2 = cmul(w2, make_float2(s02.x - s13.x, s02.y - s13.y));
        const float2 o3 = cmul(w3, make_float2(d02.x + d13.y, d02.y - d13.x));
        float4* p = (float4*)&bufA[4 * tid];
        p[0] = make_float4(o0.x, o0.y, o1.x, o1.y);
        p[1] = make_float4(o2.x, o2.y, o3.x, o3.y);
    }
    __syncthreads();

    // ---- middle stages s = 4, 16, 64 (plain smem, same pattern as R13) ----
    float2* src = bufA;
    float2* dst = bufB;
#pragma unroll
    for (int st = 1; st < 4; st++) {
        const int s = 1 << (2 * st);
        const int i = tid;
        const int q = i & (s - 1);
        const int p = i >> (2 * st);
        const float2 a0 = src[i];
        const float2 a1 = src[i + 256];
        const float2 a2 = src[i + 512];
        const float2 a3 = src[i + 768];
        const float2 w1 = tw[i - q];
        const float2 w2 = cmul(w1, w1);
        const float2 w3 = cmul(w2, w1);
        const float2 s02 = make_float2(a0.x + a2.x, a0.y + a2.y);
        const float2 d02 = make_float2(a0.x - a2.x, a0.y - a2.y);
        const float2 s13 = make_float2(a1.x + a3.x, a1.y + a3.y);
        const float2 d13 = make_float2(a1.x - a3.x, a1.y - a3.y);
        const int j0 = q + 4 * s * p;
        dst[j0]         = make_float2(s02.x + s13.x, s02.y + s13.y);
        dst[j0 + s]     = cmul(w1, make_float2(d02.x - d13.y, d02.y + d13.x));
        dst[j0 + 2 * s] = cmul(w2, make_float2(s02.x - s13.x, s02.y - s13.y));
        dst[j0 + 3 * s] = cmul(w3, make_float2(d02.x + d13.y, d02.y - d13.x));
        __syncthreads();
        float2* tmp = src; src = dst; dst = tmp;
    }
    // after 3 swaps: src == bufB

    // ---- final stage s=256 (identity twiddles) fused with output ----
    {
        const float2 a0 = src[tid];
        const float2 a1 = src[tid + 256];
        const float2 a2 = src[tid + 512];
        const float2 a3 = src[tid + 768];
        const float2 s02 = make_float2(a0.x + a2.x, a0.y + a2.y);
        const float2 d02 = make_float2(a0.x - a2.x, a0.y - a2.y);
        const float2 s13 = make_float2(a1.x + a3.x, a1.y + a3.y);
        const float2 d13 = make_float2(a1.x - a3.x, a1.y - a3.y);
        float2 zz[4];
        zz[0] = make_float2(s02.x + s13.x, s02.y + s13.y);
        zz[1] = make_float2(d02.x - d13.y, d02.y + d13.x);
        zz[2] = make_float2(s02.x - s13.x, s02.y - s13.y);
        zz[3] = make_float2(d02.x + d13.y, d02.y - d13.x);

        const float invn = 1.0f / (float)NFFT;
        float2* out2 = (float2*)&g_s[(size_t)frame * NFFT];
        const float2* winv = (const float2*)win;
#pragma unroll
        for (int c = 0; c < 4; c++) {
            const int n = tid + 256 * c;          // x[2n]=Re z[n], x[2n+1]=Im z[n]
            const float2 w = __ldg(winv + n);
            out2[n] = make_float2(zz[c].x * w.x * invn, zz[c].y * w.y * invn);
        }
    }
}

// ---------------- kernel 2: overlap-add + wss normalize ---------------------
// Interior: exactly 4 frames, wss == 1.5 exactly (hann COLA @75%) -> sum*2/3.
__global__ void __launch_bounds__(256)
oa_kernel(const float* __restrict__ win, float* __restrict__ out,
          int nf, int length) {
    const int nq = length >> 2;
    int id = blockIdx.x * blockDim.x + threadIdx.x;
    if (id >= BATCH * nq) return;
    int b = id / nq;
    int q = (id - b * nq) << 2;
    int p = q + NFFT / 2;

    if (q >= HOPLEN && q < length - HOPLEN) {     // interior fast path
        const int thi = p >> 9;
        const int o0  = p - (thi << 9);
        const size_t rb = ((size_t)(b * nf + thi - 3)) * NFFT;
        const float4 v0 = *(const float4*)&g_s[rb + o0 + 1536];
        const float4 v1 = *(const float4*)&g_s[rb + NFFT + o0 + 1024];
        const float4 v2 = *(const float4*)&g_s[rb + 2 * NFFT + o0 + 512];
        const float4 v3 = *(const float4*)&g_s[rb + 3 * NFFT + o0];
        const float c = 2.0f / 3.0f;
        float4 r;
        r.x = (v0.x + v1.x + v2.x + v3.x) * c;
        r.y = (v0.y + v1.y + v2.y + v3.y) * c;
        r.z = (v0.z + v1.z + v2.z + v3.z) * c;
        r.w = (v0.w + v1.w + v2.w + v3.w) * c;
        *(float4*)&out[(size_t)b * length + q] = r;
    } else {                                      // boundary general path
        float r[4];
#pragma unroll
        for (int j = 0; j < 4; j++) {
            const int pp = p + j;
            const int thi = pp >> 9;
            int tlo = thi - 3; if (tlo < 0) tlo = 0;
            int tup = thi;     if (tup > nf - 1) tup = nf - 1;
            float acc = 0.f, wss = 0.f;
            for (int t = tlo; t <= tup; t++) {
                const int o = pp - (t << 9);
                const float w = __ldg(win + o);
                wss += w * w;
                acc += g_s[((size_t)(b * nf + t)) * NFFT + o];
            }
            r[j] = (wss > 1.17549435e-38f) ? (acc / wss) : acc;
        }
        *(float4*)&out[(size_t)b * length + q] = make_float4(r[0], r[1], r[2], r[3]);
    }
}

// ---------------------------------------------------------------------------
extern "C" void kernel_launch(void* const* d_in, const int* in_sizes, int n_in,
                              void* d_out, int out_size) {
    const float* real_stft = (const float*)d_in[0];
    const float* imag_stft = (const float*)d_in[1];
    const float* window    = (const float*)d_in[4];

    const int T      = in_sizes[0] / (BATCH * FREQ);        // 1000
    const int length = out_size / BATCH;                    // 511488
    int nf = (length + NFFT + HOPLEN - 1) / HOPLEN;
    if (nf > T) nf = T;                                     // 1000

    ifft_kernel<<<BATCH * nf, 256>>>(real_stft, imag_stft, window, T, nf);
    {
        int total = BATCH * (length >> 2);
        oa_kernel<<<(total + 255) / 256, 256>>>(window, (float*)d_out, nf, length);
    }
}

// round 17
// speedup vs baseline: 1.3906x; 1.3906x over previous
#include <cuda_runtime.h>
#include <cstdint>

// ISTFT via half-size complex IFFT (radix-4 Stockham on 1024 pts, 5 smem
// stages — the proven R13 structure) with bank-conflict padding on the
// ping-pong buffers. Then COLA overlap-add (interior wss == 1.5 exactly).
// Shapes: B=8, T=1000, F=1025, NFFT=2048, HOP=512.

#define NFFT   2048
#define FREQ   1025
#define HOPLEN 512
#define BATCH  8
#define N2     1024

// pad: +2 float2 per 16 -> breaks the 128B-periodic write patterns
#define PHYS(j) ((j) + 2 * ((j) >> 4))
#define BUFSZ   1152          // PHYS(1023) = 1149

__device__ __align__(256) float g_s[(size_t)BATCH * 1000 * NFFT];

__device__ __forceinline__ float2 cmul(float2 a, float2 b) {
    return make_float2(a.x * b.x - a.y * b.y, a.x * b.y + a.y * b.x);
}

// ---------------- kernel 1: per-frame windowed real IFFT --------------------
__global__ void __launch_bounds__(256)
ifft_kernel(const float* __restrict__ re, const float* __restrict__ im,
            const float* __restrict__ win, int T, int nf) {
    __shared__ float2 bufA[BUFSZ];
    __shared__ float2 bufB[BUFSZ];
    __shared__ float2 tw[256];        // e^{+2pi i j / 1024}

    const int frame = blockIdx.x;
    const int b = frame / nf;
    const int t = frame - b * nf;
    const size_t base = (size_t)(b * T + t) * FREQ;
    const int tid = threadIdx.x;

    // twiddles: stage table + pack twiddle, 2 sincospif per thread
    float2 tw2;
    {
        float s, c;
        sincospif((float)tid / 512.0f, &s, &c);   // 2*pi*tid/1024
        tw[tid] = make_float2(c, s);
        sincospif((float)tid / 1024.0f, &s, &c);  // 2*pi*tid/2048
        tw2 = make_float2(c, s);
    }

    const float R = 0.70710678118654752f;
    const float2 rot[4] = { make_float2(1.f, 0.f), make_float2(R, R),
                            make_float2(0.f, 1.f), make_float2(-R, R) };

    // pack Z -> bufA :  Z[k] = (F[k]+F[k+1024]) + i*(F[k]-F[k+1024])*e^{2pi ik/2048}
#pragma unroll
    for (int u = 0; u < 4; u++) {
        const int k = tid + u * 256;              // 0..1023
        float2 Fk, F2;
        if (k == 0) {
            Fk = make_float2(__ldg(re + base), 0.f);
            F2 = make_float2(__ldg(re + base + N2), 0.f);
        } else {
            Fk = make_float2(__ldg(re + base + k), __ldg(im + base + k));
            F2 = make_float2(__ldg(re + base + (N2 - k)),
                             -__ldg(im + base + (N2 - k)));
        }
        const float2 A  = make_float2(Fk.x + F2.x, Fk.y + F2.y);
        const float2 Bc = make_float2(Fk.x - F2.x, Fk.y - F2.y);
        const float2 w  = cmul(tw2, rot[u]);      // e^{+2pi i k/2048}
        const float2 Bt = cmul(Bc, w);
        bufA[PHYS(k)] = make_float2(A.x - Bt.y, A.y + Bt.x);   // A + i*B
    }
    __syncthreads();

    // radix-4 Stockham, 5 stages (s = 1,4,16,64,256), one butterfly/thread
    float2* src = bufA;
    float2* dst = bufB;
#pragma unroll
    for (int st = 0; st < 5; st++) {
        const int s = 1 << (2 * st);
        const int i = tid;
        const int q = i & (s - 1);
        const int p = i >> (2 * st);
        const float2 a0 = src[PHYS(i)];
        const float2 a1 = src[PHYS(i + 256)];
        const float2 a2 = src[PHYS(i + 512)];
        const float2 a3 = src[PHYS(i + 768)];
        const float2 w1 = tw[i - q];
        const float2 w2 = cmul(w1, w1);
        const float2 w3 = cmul(w2, w1);
        const float2 s02 = make_float2(a0.x + a2.x, a0.y + a2.y);
        const float2 d02 = make_float2(a0.x - a2.x, a0.y - a2.y);
        const float2 s13 = make_float2(a1.x + a3.x, a1.y + a3.y);
        const float2 d13 = make_float2(a1.x - a3.x, a1.y - a3.y);
        const float2 b0 = make_float2(s02.x + s13.x, s02.y + s13.y);
        const float2 b1 = make_float2(d02.x - d13.y, d02.y + d13.x);
        const float2 b2 = make_float2(s02.x - s13.x, s02.y - s13.y);
        const float2 b3 = make_float2(d02.x + d13.y, d02.y - d13.x);
        const int j0 = q + 4 * s * p;
        dst[PHYS(j0)]         = b0;
        dst[PHYS(j0 + s)]     = cmul(w1, b1);
        dst[PHYS(j0 + 2 * s)] = cmul(w2, b2);
        dst[PHYS(j0 + 3 * s)] = cmul(w3, b3);
        __syncthreads();
        float2* tmp = src; src = dst; dst = tmp;
    }
    // result in src (bufB after 5 swaps)

    // unpack: x[2n]=Re z[n], x[2n+1]=Im z[n]; scale by win/N
    const float invn = 1.0f / (float)NFFT;
    float2* out2 = (float2*)&g_s[(size_t)frame * NFFT];
    const float2* winv = (const float2*)win;
#pragma unroll
    for (int u = 0; u < 4; u++) {
        const int n = tid + u * 256;
        const float2 z = src[PHYS(n)];
        const float2 w = __ldg(winv + n);
        out2[n] = make_float2(z.x * w.x * invn, z.y * w.y * invn);
    }
}

// ---------------- kernel 2: overlap-add + wss normalize ---------------------
// Interior: exactly 4 frames, wss == 1.5 exactly (hann COLA @75%) -> sum*2/3.
__global__ void __launch_bounds__(256)
oa_kernel(const float* __restrict__ win, float* __restrict__ out,
          int nf, int length) {
    const int nq = length >> 2;
    int id = blockIdx.x * blockDim.x + threadIdx.x;
    if (id >= BATCH * nq) return;
    int b = id / nq;
    int q = (id - b * nq) << 2;
    int p = q + NFFT / 2;

    if (q >= HOPLEN && q < length - HOPLEN) {     // interior fast path
        const int thi = p >> 9;
        const int o0  = p - (thi << 9);
        const size_t rb = ((size_t)(b * nf + thi - 3)) * NFFT;
        const float4 v0 = *(const float4*)&g_s[rb + o0 + 1536];
        const float4 v1 = *(const float4*)&g_s[rb + NFFT + o0 + 1024];
        const float4 v2 = *(const float4*)&g_s[rb + 2 * NFFT + o0 + 512];
        const float4 v3 = *(const float4*)&g_s[rb + 3 * NFFT + o0];
        const float c = 2.0f / 3.0f;
        float4 r;
        r.x = (v0.x + v1.x + v2.x + v3.x) * c;
        r.y = (v0.y + v1.y + v2.y + v3.y) * c;
        r.z = (v0.z + v1.z + v2.z + v3.z) * c;
        r.w = (v0.w + v1.w + v2.w + v3.w) * c;
        *(float4*)&out[(size_t)b * length + q] = r;
    } else {                                      // boundary general path
        float r[4];
#pragma unroll
        for (int j = 0; j < 4; j++) {
            const int pp = p + j;
            const int thi = pp >> 9;
            int tlo = thi - 3; if (tlo < 0) tlo = 0;
            int tup = thi;     if (tup > nf - 1) tup = nf - 1;
            float acc = 0.f, wss = 0.f;
            for (int t = tlo; t <= tup; t++) {
                const int o = pp - (t << 9);
                const float w = __ldg(win + o);
                wss += w * w;
                acc += g_s[((size_t)(b * nf + t)) * NFFT + o];
            }
            r[j] = (wss > 1.17549435e-38f) ? (acc / wss) : acc;
        }
        *(float4*)&out[(size_t)b * length + q] = make_float4(r[0], r[1], r[2], r[3]);
    }
}

// ---------------------------------------------------------------------------
extern "C" void kernel_launch(void* const* d_in, const int* in_sizes, int n_in,
                              void* d_out, int out_size) {
    const float* real_stft = (const float*)d_in[0];
    const float* imag_stft = (const float*)d_in[1];
    const float* window    = (const float*)d_in[4];

    const int T      = in_sizes[0] / (BATCH * FREQ);        // 1000
    const int length = out_size / BATCH;                    // 511488
    int nf = (length + NFFT + HOPLEN - 1) / HOPLEN;
    if (nf > T) nf = T;                                     // 1000

    ifft_kernel<<<BATCH * nf, 256>>>(real_stft, imag_stft, window, T, nf);
    {
        int total = BATCH * (length >> 2);
        oa_kernel<<<(total + 255) / 256, 256>>>(window, (float*)d_out, nf, length);
    }
}